// round 13
// baseline (speedup 1.0000x reference)
#include <cuda_runtime.h>
#include <math.h>
#include <float.h>

// Problem dims
#define LSRC 256
#define BATCH 64
#define HID 512
#define GATES 2048     // 4*HID
#define VOCAB 32000
#define TDEC 32
#define MAXGRID 160

// ---------------- scratch (device globals; no allocation allowed) ----------------
__device__ float g_xproj[(size_t)LSRC * BATCH * GATES];   // 134 MB
__device__ float g_hs[(size_t)LSRC * BATCH * HID];        // 33.5 MB
__device__ float g_hsW[(size_t)LSRC * BATCH * HID];       // 33.5 MB
__device__ float g_hT0[HID * BATCH];   // transposed h [k][b]
__device__ float g_hT1[HID * BATCH];
__device__ float g_cT[HID * BATCH];    // transposed c [j][b]
__device__ float g_dT0[HID * BATCH];
__device__ float g_dT1[HID * BATCH];
__device__ float g_hdrow[BATCH * HID];
__device__ float g_xT[HID * BATCH];    // decoder input emb, transposed
__device__ float g_ctxT[HID * BATCH];
__device__ float g_attT[HID * BATCH];
__device__ float g_partV[MAXGRID * BATCH];
__device__ int   g_partI[MAXGRID * BATCH];
__device__ unsigned g_arr[MAXGRID * 32];   // decoder barrier flags
__device__ unsigned g_gen = 0;
__device__ unsigned g_arrA[MAXGRID * 32];  // encoder half-A flags
__device__ unsigned g_arrB[MAXGRID * 32];  // encoder half-B flags
__device__ unsigned g_genA = 0;
__device__ unsigned g_genB = 0;

__device__ __forceinline__ float sigf(float x) { return 1.0f / (1.0f + expf(-x)); }

// ---------------- packed fp32x2 FMA ----------------
__device__ __forceinline__ void ffma2(unsigned long long& d, unsigned long long a,
                                      unsigned long long b) {
    asm("fma.rn.f32x2 %0, %1, %2, %0;" : "+l"(d) : "l"(a), "l"(b));
}
__device__ __forceinline__ unsigned long long pack2(float x) {
    unsigned long long r;
    asm("mov.b64 %0, {%1, %1};" : "=l"(r) : "r"(__float_as_uint(x)));
    return r;
}
__device__ __forceinline__ float2 unpack2(unsigned long long v) {
    unsigned lo, hi;
    asm("mov.b64 {%0, %1}, %2;" : "=r"(lo), "=r"(hi) : "l"(v));
    return make_float2(__uint_as_float(lo), __uint_as_float(hi));
}

// ---------------- acquire/release primitives ----------------
__device__ __forceinline__ unsigned ld_acq(const unsigned* p) {
    unsigned v;
    asm volatile("ld.acquire.gpu.global.u32 %0, [%1];" : "=r"(v) : "l"(p) : "memory");
    return v;
}
__device__ __forceinline__ void st_rel(unsigned* p, unsigned v) {
    asm volatile("st.release.gpu.global.u32 [%0], %1;" :: "l"(p), "r"(v) : "memory");
}

// ---------------- monolithic grid barrier (decoder) ----------------
__device__ __forceinline__ void gridbar(unsigned nb, unsigned& mygen) {
    const unsigned target = mygen + 1u;
    __syncthreads();
    if (blockIdx.x == 0) {
        if (threadIdx.x > 0 && threadIdx.x < nb) {
            while (ld_acq(&g_arr[threadIdx.x * 32]) < target) {}
        }
        __syncthreads();
        if (threadIdx.x == 0) st_rel(&g_gen, target);
    } else {
        if (threadIdx.x == 0) {
            st_rel(&g_arr[blockIdx.x * 32], target);
            while (ld_acq(&g_gen) < target) {}
        }
        __syncthreads();
    }
    mygen = target;
}

// ---------------- split barrier: arrive / wait (encoder pipelining) ----------------
__device__ __forceinline__ void bar_arrive(unsigned* arr, unsigned target) {
    __syncthreads();                      // block writes done before release
    if (threadIdx.x == 0 && blockIdx.x != 0) st_rel(&arr[blockIdx.x * 32], target);
}
__device__ __forceinline__ void bar_wait(unsigned* arr, unsigned* gen,
                                         unsigned nb, unsigned target) {
    if (blockIdx.x == 0) {
        if (threadIdx.x > 0 && threadIdx.x < nb) {
            while (ld_acq(&arr[threadIdx.x * 32]) < target) {}
        }
        __syncthreads();
        if (threadIdx.x == 0) st_rel(gen, target);
    } else {
        if (threadIdx.x == 0) {
            while (ld_acq(gen) < target) {}
        }
        __syncthreads();
    }
}

// ---------------- init ----------------
__global__ void init_kernel(float* hT0, float* cT) {
    int i = blockIdx.x * 256 + threadIdx.x;
    hT0[i] = 0.0f;
    cT[i] = 0.0f;
}

// ---------------- SGEMM: C[M][N] = A @ B^T (+bias1+bias2), B is [N][K], f32x2 ----------------
template<bool GATHER>
__global__ void gemm_nt(const float* __restrict__ A, const int* __restrict__ aidx,
                        const float* __restrict__ B,
                        const float* __restrict__ bias1, const float* __restrict__ bias2,
                        float* __restrict__ C, int M, int N, int K)
{
    __shared__ float As[16][68];
    __shared__ float Bs[16][68];
    __shared__ int ridx[64];
    const int m0 = blockIdx.y * 64, n0 = blockIdx.x * 64;
    const int t = threadIdx.x;
    if (GATHER) {
        if (t < 64) ridx[t] = aidx[m0 + t];
        __syncthreads();
    }
    const int tx = t & 15, ty = t >> 4;
    unsigned long long acc2[4][2];
#pragma unroll
    for (int i = 0; i < 4; i++) { acc2[i][0] = 0ull; acc2[i][1] = 0ull; }
    const int lm = t >> 2, lk = (t & 3) * 4;
    for (int k0 = 0; k0 < K; k0 += 16) {
        const float* arow = A + (size_t)(GATHER ? ridx[lm] : (m0 + lm)) * K + k0 + lk;
        float4 av = *(const float4*)arow;
        As[lk + 0][lm] = av.x; As[lk + 1][lm] = av.y; As[lk + 2][lm] = av.z; As[lk + 3][lm] = av.w;
        float4 bv = *(const float4*)(B + (size_t)(n0 + lm) * K + k0 + lk);
        Bs[lk + 0][lm] = bv.x; Bs[lk + 1][lm] = bv.y; Bs[lk + 2][lm] = bv.z; Bs[lk + 3][lm] = bv.w;
        __syncthreads();
#pragma unroll
        for (int kk = 0; kk < 16; kk++) {
            float4 a4 = *(const float4*)&As[kk][ty * 4];
            ulonglong2 b2 = *(const ulonglong2*)&Bs[kk][tx * 4];
            float aa[4] = {a4.x, a4.y, a4.z, a4.w};
#pragma unroll
            for (int i = 0; i < 4; i++) {
                unsigned long long ap = pack2(aa[i]);
                ffma2(acc2[i][0], ap, b2.x);
                ffma2(acc2[i][1], ap, b2.y);
            }
        }
        __syncthreads();
    }
#pragma unroll
    for (int i = 0; i < 4; i++) {
        int m = m0 + ty * 4 + i;
        float2 f0 = unpack2(acc2[i][0]);
        float2 f1 = unpack2(acc2[i][1]);
        float vj[4] = {f0.x, f0.y, f1.x, f1.y};
#pragma unroll
        for (int j = 0; j < 4; j++) {
            int n = n0 + tx * 4 + j;
            float v = vj[j];
            if (bias1) v += bias1[n];
            if (bias2) v += bias2[n];
            C[(size_t)m * N + n] = v;
        }
    }
}

// ---------------- SGEMM: C[M][N] = A @ B, B is [K][N], f32x2 ----------------
__global__ void gemm_nn(const float* __restrict__ A, const float* __restrict__ B,
                        float* __restrict__ C, int M, int N, int K)
{
    __shared__ float As[16][68];
    __shared__ float Bs[16][68];
    const int m0 = blockIdx.y * 64, n0 = blockIdx.x * 64;
    const int t = threadIdx.x;
    const int tx = t & 15, ty = t >> 4;
    unsigned long long acc2[4][2];
#pragma unroll
    for (int i = 0; i < 4; i++) { acc2[i][0] = 0ull; acc2[i][1] = 0ull; }
    const int lm = t >> 2, lk = (t & 3) * 4;
    const int bk = t >> 4, bn = (t & 15) * 4;
    for (int k0 = 0; k0 < K; k0 += 16) {
        float4 av = *(const float4*)(A + (size_t)(m0 + lm) * K + k0 + lk);
        As[lk + 0][lm] = av.x; As[lk + 1][lm] = av.y; As[lk + 2][lm] = av.z; As[lk + 3][lm] = av.w;
        float4 bv = *(const float4*)(B + (size_t)(k0 + bk) * N + n0 + bn);
        *(float4*)&Bs[bk][bn] = bv;
        __syncthreads();
#pragma unroll
        for (int kk = 0; kk < 16; kk++) {
            float4 a4 = *(const float4*)&As[kk][ty * 4];
            ulonglong2 b2 = *(const ulonglong2*)&Bs[kk][tx * 4];
            float aa[4] = {a4.x, a4.y, a4.z, a4.w};
#pragma unroll
            for (int i = 0; i < 4; i++) {
                unsigned long long ap = pack2(aa[i]);
                ffma2(acc2[i][0], ap, b2.x);
                ffma2(acc2[i][1], ap, b2.y);
            }
        }
        __syncthreads();
    }
#pragma unroll
    for (int i = 0; i < 4; i++) {
        int m = m0 + ty * 4 + i;
        float2 f0 = unpack2(acc2[i][0]);
        float2 f1 = unpack2(acc2[i][1]);
        C[(size_t)m * N + (n0 + tx * 4 + 0)] = f0.x;
        C[(size_t)m * N + (n0 + tx * 4 + 1)] = f0.y;
        C[(size_t)m * N + (n0 + tx * 4 + 2)] = f1.x;
        C[(size_t)m * N + (n0 + tx * 4 + 3)] = f1.y;
    }
}

// ---------------- persistent encoder v6: batch-split A/B pipeline, split barriers ----------------
// Half = 32 batches. Thread (kq = t>>5 in 0..15 -> 32 k; lb = t&31). 16 accumulators (f32x2 x8).
// Sequence/step: A GEMV+cell, arrive_A, wait_B(t-1), B GEMV+cell, arrive_B, wait_A(t).
// Barrier round-trips hide behind the other half's compute.
// dyn smem: wsm[512*16=8192] | psum[16*32*17=8704]
__global__ __launch_bounds__(512, 1) void enc_persist(
    const float* __restrict__ xproj, const float* __restrict__ Whh,
    const int* __restrict__ src,
    float* __restrict__ hT0, float* __restrict__ hT1,
    float* __restrict__ cT, float* __restrict__ hs)
{
    extern __shared__ float esm[];
    float* wsm = esm;            // [k][16]
    float* psum = esm + 8192;    // [(kq*32+lb)*17 + c]
    const int t = threadIdx.x, bn = blockIdx.x;
    const unsigned nb = gridDim.x;
    const unsigned baseA = ld_acq(&g_genA);
    const unsigned baseB = ld_acq(&g_genB);

    for (int i = t; i < 512 * 16; i += 512) {
        int c = i & 15, k = i >> 4;
        int q = c >> 2, jj = c & 3;
        wsm[k * 16 + c] = Whh[(size_t)(q * 512 + bn * 4 + jj) * 512 + k];
    }
    __syncthreads();

    const int kq = t >> 5, lb = t & 31, k0 = kq * 32;
    float* psbase = psum + (size_t)(kq * 32 + lb) * 17;
    const int ebl = t >> 2, ejj = t & 3, ej = bn * 4 + ejj;  // epilogue roles (t<128)

    for (int tt = 0; tt < LSRC; tt++) {
        const float* hin = (tt & 1) ? hT1 : hT0;
        float* hout = (tt & 1) ? hT0 : hT1;
        const float* xp = xproj + (size_t)tt * 64 * 2048;
        float xa0 = 0.f, xa1 = 0.f, xa2 = 0.f, xa3 = 0.f;
        float xb0 = 0.f, xb1 = 0.f, xb2 = 0.f, xb3 = 0.f;
        if (t < 128) {
            const float* xpa = xp + (size_t)ebl * 2048 + bn * 4 + ejj;
            xa0 = xpa[0]; xa1 = xpa[512]; xa2 = xpa[1024]; xa3 = xpa[1536];
            const float* xpb = xp + (size_t)(32 + ebl) * 2048 + bn * 4 + ejj;
            xb0 = xpb[0]; xb1 = xpb[512]; xb2 = xpb[1024]; xb3 = xpb[1536];
        }

        // ================= half A (batches 0..31) =================
        {
            unsigned long long accp[8];
#pragma unroll
            for (int p = 0; p < 8; p++) accp[p] = 0ull;
            const float* hp = hin + (size_t)k0 * 64 + lb;
#pragma unroll
            for (int k = 0; k < 32; k += 8) {
                float hreg[8];
#pragma unroll
                for (int u = 0; u < 8; u++) hreg[u] = hp[(k + u) * 64];
#pragma unroll
                for (int u = 0; u < 8; u++) {
                    const ulonglong2* w2 = (const ulonglong2*)(wsm + (size_t)(k0 + k + u) * 16);
                    ulonglong2 wa = w2[0], wb = w2[1], wc = w2[2], wd = w2[3];
                    unsigned long long h2 = pack2(hreg[u]);
                    ffma2(accp[0], h2, wa.x); ffma2(accp[1], h2, wa.y);
                    ffma2(accp[2], h2, wb.x); ffma2(accp[3], h2, wb.y);
                    ffma2(accp[4], h2, wc.x); ffma2(accp[5], h2, wc.y);
                    ffma2(accp[6], h2, wd.x); ffma2(accp[7], h2, wd.y);
                }
            }
#pragma unroll
            for (int p = 0; p < 8; p++) {
                float2 f = unpack2(accp[p]);
                psbase[2 * p] = f.x;
                psbase[2 * p + 1] = f.y;
            }
            __syncthreads();
            if (t < 128) {
                float gi = xa0, gf = xa1, gg = xa2, go = xa3;
#pragma unroll
                for (int r = 0; r < 16; r++) {
                    const float* pr = psum + (size_t)(r * 32 + ebl) * 17;
                    gi += pr[ejj];
                    gf += pr[4 + ejj];
                    gg += pr[8 + ejj];
                    go += pr[12 + ejj];
                }
                float cold = cT[ej * 64 + ebl];
                float cn = sigf(gf) * cold + sigf(gi) * tanhf(gg);
                float hn = sigf(go) * tanhf(cn);
                float m = (src[tt * 64 + ebl] > 0) ? 1.0f : 0.0f;
                hout[ej * 64 + ebl] = m * hn + (1.0f - m) * hin[ej * 64 + ebl];
                cT[ej * 64 + ebl] = m * cn + (1.0f - m) * cold;
                hs[((size_t)tt * 64 + ebl) * 512 + ej] = hn * m;
            }
        }
        bar_arrive(g_arrA, baseA + tt + 1);
        if (tt > 0) bar_wait(g_arrB, &g_genB, nb, baseB + tt);

        // ================= half B (batches 32..63) =================
        {
            unsigned long long accp[8];
#pragma unroll
            for (int p = 0; p < 8; p++) accp[p] = 0ull;
            const float* hp = hin + (size_t)k0 * 64 + 32 + lb;
#pragma unroll
            for (int k = 0; k < 32; k += 8) {
                float hreg[8];
#pragma unroll
                for (int u = 0; u < 8; u++) hreg[u] = hp[(k + u) * 64];
#pragma unroll
                for (int u = 0; u < 8; u++) {
                    const ulonglong2* w2 = (const ulonglong2*)(wsm + (size_t)(k0 + k + u) * 16);
                    ulonglong2 wa = w2[0], wb = w2[1], wc = w2[2], wd = w2[3];
                    unsigned long long h2 = pack2(hreg[u]);
                    ffma2(accp[0], h2, wa.x); ffma2(accp[1], h2, wa.y);
                    ffma2(accp[2], h2, wb.x); ffma2(accp[3], h2, wb.y);
                    ffma2(accp[4], h2, wc.x); ffma2(accp[5], h2, wc.y);
                    ffma2(accp[6], h2, wd.x); ffma2(accp[7], h2, wd.y);
                }
            }
            __syncthreads();   // A-epilogue psum reads done (also covered by arrive's sync)
#pragma unroll
            for (int p = 0; p < 8; p++) {
                float2 f = unpack2(accp[p]);
                psbase[2 * p] = f.x;
                psbase[2 * p + 1] = f.y;
            }
            __syncthreads();
            if (t < 128) {
                const int gb = 32 + ebl;
                float gi = xb0, gf = xb1, gg = xb2, go = xb3;
#pragma unroll
                for (int r = 0; r < 16; r++) {
                    const float* pr = psum + (size_t)(r * 32 + ebl) * 17;
                    gi += pr[ejj];
                    gf += pr[4 + ejj];
                    gg += pr[8 + ejj];
                    go += pr[12 + ejj];
                }
                float cold = cT[ej * 64 + gb];
                float cn = sigf(gf) * cold + sigf(gi) * tanhf(gg);
                float hn = sigf(go) * tanhf(cn);
                float m = (src[tt * 64 + gb] > 0) ? 1.0f : 0.0f;
                hout[ej * 64 + gb] = m * hn + (1.0f - m) * hin[ej * 64 + gb];
                cT[ej * 64 + gb] = m * cn + (1.0f - m) * cold;
                hs[((size_t)tt * 64 + gb) * 512 + ej] = hn * m;
            }
        }
        bar_arrive(g_arrB, baseB + tt + 1);
        bar_wait(g_arrA, &g_genA, nb, baseA + tt + 1);
    }
}

// ---------------- persistent decoder: 512 threads, all 32 steps, f32x2 (R11) ----------------
#define DEC_POOL_OFF 16400
#define DEC_POOL_FLOATS 36992
#define DEC_SMEM_FLOATS (DEC_POOL_OFF + DEC_POOL_FLOATS)

__global__ __launch_bounds__(512, 1) void dec_persist(
    const float* __restrict__ dec_emb,
    const float* __restrict__ Wih, const float* __restrict__ Whh,
    const float* __restrict__ bih, const float* __restrict__ bhh,
    const float* __restrict__ Wc, const float* __restrict__ bc,
    const float* __restrict__ outW, const float* __restrict__ outb,
    const float* __restrict__ hsW, const float* __restrict__ hs,
    const int* __restrict__ src,
    const float* __restrict__ encH,
    float* __restrict__ dT0, float* __restrict__ dT1, float* __restrict__ cT,
    float* __restrict__ hdrow, float* __restrict__ xT,
    float* __restrict__ ctxT, float* __restrict__ attT,
    float* __restrict__ partV, int* __restrict__ partI,
    float* __restrict__ out)
{
    extern __shared__ float dyn[];
    float* wih_s = dyn;          // [k][16]
    float* whh_s = dyn + 8192;   // [k][16]
    float* bsum = dyn + 16384;   // [16]
    float* pool = dyn + DEC_POOL_OFF;

    const int t = threadIdx.x, bid = blockIdx.x;
    const unsigned gd = gridDim.x;
    unsigned mygen = ld_acq(&g_gen);

    if (bid < 128) {
        for (int i = t; i < 512 * 16; i += 512) {
            int c = i & 15, k = i >> 4;
            int q = c >> 2, jj = c & 3;
            int gc = q * 512 + bid * 4 + jj;
            wih_s[k * 16 + c] = Wih[(size_t)gc * 512 + k];
            whh_s[k * 16 + c] = Whh[(size_t)gc * 512 + k];
        }
        if (t < 16) {
            int q = t >> 2, jj = t & 3;
            int gc = q * 512 + bid * 4 + jj;
            bsum[t] = bih[gc] + bhh[gc];
        }
    }
    if (bid < 64) {
        xT[t * 64 + bid] = dec_emb[512 + t];   // row BOS=1
    }
    gridbar(gd, mygen);

    const int b = t & 63, kq = t >> 6, k0 = kq * 64;
    const int eb = t >> 2, ejj = t & 3;

    for (int s = 0; s < TDEC; s++) {
        const float* hdin = (s == 0) ? encH : ((s & 1) ? dT1 : dT0);
        float* hdout = (s & 1) ? dT0 : dT1;

        // ---- phase A: decoder LSTM cell (f32x2) ----
        if (bid < 128) {
            unsigned long long accp[8];
#pragma unroll
            for (int p = 0; p < 8; p++) accp[p] = 0ull;
            const float* xp = xT + (size_t)k0 * 64 + b;
#pragma unroll
            for (int k = 0; k < 64; k += 8) {
                float xreg[8];
#pragma unroll
                for (int u = 0; u < 8; u++) xreg[u] = xp[(k + u) * 64];
#pragma unroll
                for (int u = 0; u < 8; u++) {
                    const ulonglong2* w2 = (const ulonglong2*)(wih_s + (size_t)(k0 + k + u) * 16);
                    ulonglong2 wa = w2[0], wb = w2[1], wc = w2[2], wd = w2[3];
                    unsigned long long h2 = pack2(xreg[u]);
                    ffma2(accp[0], h2, wa.x); ffma2(accp[1], h2, wa.y);
                    ffma2(accp[2], h2, wb.x); ffma2(accp[3], h2, wb.y);
                    ffma2(accp[4], h2, wc.x); ffma2(accp[5], h2, wc.y);
                    ffma2(accp[6], h2, wd.x); ffma2(accp[7], h2, wd.y);
                }
            }
            const float* hp = hdin + (size_t)k0 * 64 + b;
#pragma unroll
            for (int k = 0; k < 64; k += 8) {
                float hreg[8];
#pragma unroll
                for (int u = 0; u < 8; u++) hreg[u] = hp[(k + u) * 64];
#pragma unroll
                for (int u = 0; u < 8; u++) {
                    const ulonglong2* w2 = (const ulonglong2*)(whh_s + (size_t)(k0 + k + u) * 16);
                    ulonglong2 wa = w2[0], wb = w2[1], wc = w2[2], wd = w2[3];
                    unsigned long long h2 = pack2(hreg[u]);
                    ffma2(accp[0], h2, wa.x); ffma2(accp[1], h2, wa.y);
                    ffma2(accp[2], h2, wb.x); ffma2(accp[3], h2, wb.y);
                    ffma2(accp[4], h2, wc.x); ffma2(accp[5], h2, wc.y);
                    ffma2(accp[6], h2, wd.x); ffma2(accp[7], h2, wd.y);
                }
            }
            {
                float* ps = pool + (size_t)(kq * 64 + b) * 17;
#pragma unroll
                for (int p = 0; p < 8; p++) {
                    float2 f = unpack2(accp[p]);
                    ps[2 * p] = f.x;
                    ps[2 * p + 1] = f.y;
                }
            }
            __syncthreads();
            if (t < 256) {
                const int j = bid * 4 + ejj;
                float gi = bsum[ejj], gf = bsum[4 + ejj], gg = bsum[8 + ejj], go = bsum[12 + ejj];
#pragma unroll
                for (int r = 0; r < 8; r++) {
                    const float* pr = pool + (size_t)(r * 64 + eb) * 17;
                    gi += pr[ejj];
                    gf += pr[4 + ejj];
                    gg += pr[8 + ejj];
                    go += pr[12 + ejj];
                }
                float cold = cT[j * 64 + eb];
                float cn = sigf(gf) * cold + sigf(gi) * tanhf(gg);
                float hn = sigf(go) * tanhf(cn);
                hdout[j * 64 + eb] = hn;
                hdrow[eb * 512 + j] = hn;
                cT[j * 64 + eb] = cn;
            }
        }
        gridbar(gd, mygen);

        // ---- phase B: attention scores + softmax + context ----
        if (bid < 64) {
            float* hd_sm = pool;
            float* sc = pool + 512;
            float* red = pool + 768;
            hd_sm[t] = hdrow[bid * 512 + t];
            __syncthreads();
            const int w = t >> 5, lane = t & 31;
            for (int l = w; l < 256; l += 16) {
                const float* hw = hsW + ((size_t)l * 64 + bid) * 512;
                float sv = 0.0f;
#pragma unroll
                for (int kk = 0; kk < 16; kk++) sv += hd_sm[lane + kk * 32] * hw[lane + kk * 32];
#pragma unroll
                for (int o = 16; o; o >>= 1) sv += __shfl_xor_sync(0xffffffffu, sv, o);
                if (lane == 0) sc[l] = sv;
            }
            __syncthreads();
            float my = 0.0f;
            if (t < 256) {
                my = sc[t];
                float v = my;
#pragma unroll
                for (int o = 16; o; o >>= 1) v = fmaxf(v, __shfl_xor_sync(0xffffffffu, v, o));
                if (lane == 0) red[w] = v;
            }
            __syncthreads();
            float mx = red[0];
#pragma unroll
            for (int i = 1; i < 8; i++) mx = fmaxf(mx, red[i]);
            if (t < 256) {
                float ev = expf(my - mx) * (src[t * 64 + bid] > 0 ? 1.0f : 0.0f);
                sc[t] = ev;
                float sv = ev;
#pragma unroll
                for (int o = 16; o; o >>= 1) sv += __shfl_xor_sync(0xffffffffu, sv, o);
                if (lane == 0) red[8 + w] = sv;
            }
            __syncthreads();
            float tot = 0.0f;
#pragma unroll
            for (int i = 0; i < 8; i++) tot += red[8 + i];
            float inv = 1.0f / tot;
            {
                float a = 0.0f;
                const float* hp2 = hs + (size_t)bid * 512 + t;
                for (int l = 0; l < 256; l++) a += sc[l] * hp2[(size_t)l * 64 * 512];
                ctxT[t * 64 + bid] = a * inv;
            }
        }
        gridbar(gd, mygen);

        // ---- phase C: attT = tanh(cat @ Wc + bc) ----
        if (bid < 128) {
            float* As = pool;
            float* Ws = pool + 64 * 68;
            const int col = t & 3, brow = t >> 2;
            float acc = 0.0f;
            for (int kc = 0; kc < 16; kc++) {
                __syncthreads();
                if (t < 256) {
#pragma unroll
                    for (int r = 0; r < 4; r++) {
                        int idx4 = t + r * 256;
                        int row = idx4 >> 4, b4 = (idx4 & 15) * 4;
                        int k = kc * 64 + row;
                        const float* sp = (k < 512) ? (ctxT + (size_t)k * 64)
                                                    : (hdout + (size_t)(k - 512) * 64);
                        *(float4*)&As[row * 68 + b4] = *(const float4*)(sp + b4);
                    }
                    {
                        int kk = t >> 2, c = t & 3;
                        Ws[kk * 4 + c] = Wc[(size_t)(kc * 64 + kk) * 512 + bid * 4 + c];
                    }
                }
                __syncthreads();
                if (t < 256) {
#pragma unroll 8
                    for (int kk = 0; kk < 64; kk++)
                        acc += As[kk * 68 + brow] * Ws[kk * 4 + col];
                }
            }
            if (t < 256)
                attT[(bid * 4 + col) * 64 + brow] = tanhf(acc + bc[bid * 4 + col]);
        }
        gridbar(gd, mygen);

        // ---- phase D: logits GEMM (f32x2) + fused argmax partials ----
        {
            float* attS = pool;                 // [512][64]
            float* BsBuf = pool + 32768;        // 2 x [16][128]
            float* rv = pool + 36864;           // [64]
            int* ri = (int*)(pool + 36928);     // [64]
            const int tx = t & 31, ty = t >> 5;
            const int dn = t >> 2, dkg = (t & 3) * 4;

            for (int i = t * 4; i < 32768; i += 2048) {
                int k = i >> 6, bb = i & 63;
                *(float4*)&attS[k * 64 + bb] = *(const float4*)(attT + (size_t)k * 64 + bb);
            }
            __syncthreads();

            float bestv[4];
            int besti[4];
#pragma unroll
            for (int i = 0; i < 4; i++) { bestv[i] = -FLT_MAX; besti[i] = 0x7fffffff; }

            for (int tile = bid; tile < VOCAB / 128; tile += gd) {
                const int n0 = tile * 128;
                const float* wrow = outW + (size_t)(n0 + dn) * 512 + dkg;
                unsigned long long acc2[4][2];
#pragma unroll
                for (int i = 0; i < 4; i++) { acc2[i][0] = 0ull; acc2[i][1] = 0ull; }
                {
                    float4 wv = *(const float4*)(wrow);
                    float* Bs0 = BsBuf;
                    Bs0[(dkg + 0) * 128 + dn] = wv.x; Bs0[(dkg + 1) * 128 + dn] = wv.y;
                    Bs0[(dkg + 2) * 128 + dn] = wv.z; Bs0[(dkg + 3) * 128 + dn] = wv.w;
                }
                __syncthreads();
                for (int c = 0; c < 32; c++) {
                    float4 wv;
                    if (c < 31) wv = *(const float4*)(wrow + (c + 1) * 16);
                    const float* Bs = BsBuf + (c & 1) * 2048;
                    const float* Ac = attS + (size_t)c * 16 * 64;
#pragma unroll
                    for (int kk = 0; kk < 16; kk++) {
                        float4 a4 = *(const float4*)&Ac[kk * 64 + ty * 4];
                        ulonglong2 b2 = *(const ulonglong2*)&Bs[kk * 128 + tx * 4];
                        float aa[4] = {a4.x, a4.y, a4.z, a4.w};
#pragma unroll
                        for (int i = 0; i < 4; i++) {
                            unsigned long long ap = pack2(aa[i]);
                            ffma2(acc2[i][0], ap, b2.x);
                            ffma2(acc2[i][1], ap, b2.y);
                        }
                    }
                    if (c < 31) {
                        float* Bn = BsBuf + ((c + 1) & 1) * 2048;
                        Bn[(dkg + 0) * 128 + dn] = wv.x; Bn[(dkg + 1) * 128 + dn] = wv.y;
                        Bn[(dkg + 2) * 128 + dn] = wv.z; Bn[(dkg + 3) * 128 + dn] = wv.w;
                    }
                    __syncthreads();
                }
#pragma unroll
                for (int i = 0; i < 4; i++) {
                    int bb2 = ty * 4 + i;
                    float2 f0 = unpack2(acc2[i][0]);
                    float2 f1 = unpack2(acc2[i][1]);
                    float vj[4] = {f0.x, f0.y, f1.x, f1.y};
#pragma unroll
                    for (int j = 0; j < 4; j++) {
                        int n = n0 + tx * 4 + j;
                        float v = vj[j] + outb[n];
                        out[((size_t)s * 64 + bb2) * VOCAB + n] = v;
                        if (v > bestv[i]) { bestv[i] = v; besti[i] = n; }
                    }
                }
            }
#pragma unroll
            for (int i = 0; i < 4; i++) {
                float v = bestv[i]; int ix = besti[i];
#pragma unroll
                for (int o = 16; o; o >>= 1) {
                    float ov = __shfl_xor_sync(0xffffffffu, v, o);
                    int oi = __shfl_xor_sync(0xffffffffu, ix, o);
                    if (ov > v || (ov == v && oi < ix)) { v = ov; ix = oi; }
                }
                bestv[i] = v; besti[i] = ix;
            }
            __syncthreads();
            if ((t & 31) == 0) {
#pragma unroll
                for (int i = 0; i < 4; i++) { rv[ty * 4 + i] = bestv[i]; ri[ty * 4 + i] = besti[i]; }
            }
            __syncthreads();
            if (t < 64) {
                partV[bid * 64 + t] = rv[t];
                partI[bid * 64 + t] = ri[t];
            }
        }
        gridbar(gd, mygen);

        // ---- phase E: global argmax + next embedding ----
        if (bid < 64) {
            float* ev = pool;
            int* ei = (int*)(pool + 512);
            float bv = -FLT_MAX; int bi = 0x7fffffff;
            for (unsigned g = t; g < gd; g += 512) {
                float v = partV[g * 64 + bid]; int ix = partI[g * 64 + bid];
                if (v > bv || (v == bv && ix < bi)) { bv = v; bi = ix; }
            }
            ev[t] = bv; ei[t] = bi;
            __syncthreads();
            for (int s2 = 256; s2; s2 >>= 1) {
                if (t < s2) {
                    float v = ev[t + s2]; int ix = ei[t + s2];
                    if (v > ev[t] || (v == ev[t] && ix < ei[t])) { ev[t] = v; ei[t] = ix; }
                }
                __syncthreads();
            }
            int ynext = ei[0];
            xT[t * 64 + bid] = dec_emb[(size_t)ynext * 512 + t];
        }
        gridbar(gd, mygen);
    }
}

// ---------------- host launch ----------------
extern "C" void kernel_launch(void* const* d_in, const int* in_sizes, int n_in,
                              void* d_out, int out_size)
{
    const int*   src     = (const int*)d_in[0];
    const float* enc_emb = (const float*)d_in[1];
    const float* enc_Wih = (const float*)d_in[2];
    const float* enc_Whh = (const float*)d_in[3];
    const float* enc_bih = (const float*)d_in[4];
    const float* enc_bhh = (const float*)d_in[5];
    const float* dec_emb = (const float*)d_in[6];
    const float* dec_Wih = (const float*)d_in[7];
    const float* dec_Whh = (const float*)d_in[8];
    const float* dec_bih = (const float*)d_in[9];
    const float* dec_bhh = (const float*)d_in[10];
    const float* W_a     = (const float*)d_in[11];
    const float* W_c     = (const float*)d_in[12];
    const float* b_c     = (const float*)d_in[13];
    const float* out_W   = (const float*)d_in[14];
    const float* out_b   = (const float*)d_in[15];
    float* out = (float*)d_out;

    float *xproj, *hs, *hsW, *hT0, *hT1, *cT, *dT0, *dT1, *hdrow, *xT, *ctxT, *attT, *partV;
    int* partI;
    cudaGetSymbolAddress((void**)&xproj, g_xproj);
    cudaGetSymbolAddress((void**)&hs, g_hs);
    cudaGetSymbolAddress((void**)&hsW, g_hsW);
    cudaGetSymbolAddress((void**)&hT0, g_hT0);
    cudaGetSymbolAddress((void**)&hT1, g_hT1);
    cudaGetSymbolAddress((void**)&cT, g_cT);
    cudaGetSymbolAddress((void**)&dT0, g_dT0);
    cudaGetSymbolAddress((void**)&dT1, g_dT1);
    cudaGetSymbolAddress((void**)&hdrow, g_hdrow);
    cudaGetSymbolAddress((void**)&xT, g_xT);
    cudaGetSymbolAddress((void**)&ctxT, g_ctxT);
    cudaGetSymbolAddress((void**)&attT, g_attT);
    cudaGetSymbolAddress((void**)&partV, g_partV);
    cudaGetSymbolAddress((void**)&partI, g_partI);

    int nsm = 148;
    cudaDeviceGetAttribute(&nsm, cudaDevAttrMultiProcessorCount, 0);
    int gdec = nsm;
    if (gdec > MAXGRID) gdec = MAXGRID;
    if (gdec < 128) gdec = 128;

    const int enc_smem = (8192 + 16 * 32 * 17) * 4;   // 67.6 KB
    cudaFuncSetAttribute(enc_persist, cudaFuncAttributeMaxDynamicSharedMemorySize, enc_smem);
    cudaFuncSetAttribute(dec_persist, cudaFuncAttributeMaxDynamicSharedMemorySize,
                         DEC_SMEM_FLOATS * 4);

    // 6-launch sequence: ncu (-s 5 -c 1 => my 4th launch) lands on enc_persist
    gemm_nt<true><<<dim3(GATES / 64, 128), 256>>>(
        enc_emb, src, enc_Wih, enc_bih, enc_bhh, xproj, LSRC * BATCH, GATES, HID);
    gemm_nt<true><<<dim3(GATES / 64, 128), 256>>>(
        enc_emb, src + 8192, enc_Wih, enc_bih, enc_bhh,
        xproj + (size_t)8192 * GATES, LSRC * BATCH, GATES, HID);

    init_kernel<<<128, 256>>>(hT0, cT);

    enc_persist<<<128, 512, enc_smem>>>(xproj, enc_Whh, src, hT0, hT1, cT, hs);

    gemm_nn<<<dim3(HID / 64, (LSRC * BATCH) / 64), 256>>>(hs, W_a, hsW, LSRC * BATCH, HID, HID);

    dec_persist<<<gdec, 512, DEC_SMEM_FLOATS * 4>>>(
        dec_emb, dec_Wih, dec_Whh, dec_bih, dec_bhh,
        W_c, b_c, out_W, out_b, hsW, hs, src,
        hT0, dT0, dT1, cT, hdrow, xT, ctxT, attT, partV, partI, out);
}

// round 14
// speedup vs baseline: 1.0242x; 1.0242x over previous
#include <cuda_runtime.h>
#include <math.h>
#include <float.h>

// Problem dims
#define LSRC 256
#define BATCH 64
#define HID 512
#define GATES 2048     // 4*HID
#define VOCAB 32000
#define TDEC 32
#define MAXGRID 160

// ---------------- scratch (device globals; no allocation allowed) ----------------
__device__ float g_xproj[(size_t)LSRC * BATCH * GATES];   // 134 MB
__device__ float g_hs[(size_t)LSRC * BATCH * HID];        // 33.5 MB
__device__ float g_hsW[(size_t)LSRC * BATCH * HID];       // 33.5 MB
__device__ float g_hT0[HID * BATCH];   // transposed h [k][b]
__device__ float g_hT1[HID * BATCH];
__device__ float g_cT[HID * BATCH];    // transposed c [j][b]
__device__ float g_dT0[HID * BATCH];
__device__ float g_dT1[HID * BATCH];
__device__ float g_hdrow[BATCH * HID];
__device__ float g_xT[HID * BATCH];    // decoder input emb, transposed
__device__ float g_ctxT[HID * BATCH];
__device__ float g_attT[HID * BATCH];
__device__ float g_partV[MAXGRID * BATCH];
__device__ int   g_partI[MAXGRID * BATCH];
__device__ unsigned g_arr[MAXGRID * 32];  // arrival flags, 128B apart
__device__ unsigned g_gen = 0;

__device__ __forceinline__ float sigf(float x) { return 1.0f / (1.0f + expf(-x)); }

// ---------------- packed fp32x2 FMA ----------------
__device__ __forceinline__ void ffma2(unsigned long long& d, unsigned long long a,
                                      unsigned long long b) {
    asm("fma.rn.f32x2 %0, %1, %2, %0;" : "+l"(d) : "l"(a), "l"(b));
}
__device__ __forceinline__ unsigned long long pack2(float x) {
    unsigned long long r;
    asm("mov.b64 %0, {%1, %1};" : "=l"(r) : "r"(__float_as_uint(x)));
    return r;
}
__device__ __forceinline__ float2 unpack2(unsigned long long v) {
    unsigned lo, hi;
    asm("mov.b64 {%0, %1}, %2;" : "=r"(lo), "=r"(hi) : "l"(v));
    return make_float2(__uint_as_float(lo), __uint_as_float(hi));
}

// ---------------- acquire/release primitives ----------------
__device__ __forceinline__ unsigned ld_acq(const unsigned* p) {
    unsigned v;
    asm volatile("ld.acquire.gpu.global.u32 %0, [%1];" : "=r"(v) : "l"(p) : "memory");
    return v;
}
__device__ __forceinline__ void st_rel(unsigned* p, unsigned v) {
    asm volatile("st.release.gpu.global.u32 [%0], %1;" :: "l"(p), "r"(v) : "memory");
}

// ---------------- grid barrier: release/acquire, no per-thread membars ----------------
__device__ __forceinline__ void gridbar(unsigned nb, unsigned& mygen) {
    const unsigned target = mygen + 1u;
    __syncthreads();
    if (blockIdx.x == 0) {
        if (threadIdx.x > 0 && threadIdx.x < nb) {
            while (ld_acq(&g_arr[threadIdx.x * 32]) < target) {}
        }
        __syncthreads();
        if (threadIdx.x == 0) st_rel(&g_gen, target);
    } else {
        if (threadIdx.x == 0) {
            st_rel(&g_arr[blockIdx.x * 32], target);
            while (ld_acq(&g_gen) < target) {}
        }
        __syncthreads();
    }
    mygen = target;
}

// ---------------- init ----------------
__global__ void init_kernel(float* hT0, float* cT) {
    int i = blockIdx.x * 256 + threadIdx.x;
    hT0[i] = 0.0f;
    cT[i] = 0.0f;
}

// ---------------- SGEMM: C[M][N] = A @ B^T (+bias1+bias2), B is [N][K], f32x2 ----------------
template<bool GATHER>
__global__ void gemm_nt(const float* __restrict__ A, const int* __restrict__ aidx,
                        const float* __restrict__ B,
                        const float* __restrict__ bias1, const float* __restrict__ bias2,
                        float* __restrict__ C, int M, int N, int K)
{
    __shared__ float As[16][68];
    __shared__ float Bs[16][68];
    __shared__ int ridx[64];
    const int m0 = blockIdx.y * 64, n0 = blockIdx.x * 64;
    const int t = threadIdx.x;
    if (GATHER) {
        if (t < 64) ridx[t] = aidx[m0 + t];
        __syncthreads();
    }
    const int tx = t & 15, ty = t >> 4;
    unsigned long long acc2[4][2];
#pragma unroll
    for (int i = 0; i < 4; i++) { acc2[i][0] = 0ull; acc2[i][1] = 0ull; }
    const int lm = t >> 2, lk = (t & 3) * 4;
    for (int k0 = 0; k0 < K; k0 += 16) {
        const float* arow = A + (size_t)(GATHER ? ridx[lm] : (m0 + lm)) * K + k0 + lk;
        float4 av = *(const float4*)arow;
        As[lk + 0][lm] = av.x; As[lk + 1][lm] = av.y; As[lk + 2][lm] = av.z; As[lk + 3][lm] = av.w;
        float4 bv = *(const float4*)(B + (size_t)(n0 + lm) * K + k0 + lk);
        Bs[lk + 0][lm] = bv.x; Bs[lk + 1][lm] = bv.y; Bs[lk + 2][lm] = bv.z; Bs[lk + 3][lm] = bv.w;
        __syncthreads();
#pragma unroll
        for (int kk = 0; kk < 16; kk++) {
            float4 a4 = *(const float4*)&As[kk][ty * 4];
            ulonglong2 b2 = *(const ulonglong2*)&Bs[kk][tx * 4];
            float aa[4] = {a4.x, a4.y, a4.z, a4.w};
#pragma unroll
            for (int i = 0; i < 4; i++) {
                unsigned long long ap = pack2(aa[i]);
                ffma2(acc2[i][0], ap, b2.x);
                ffma2(acc2[i][1], ap, b2.y);
            }
        }
        __syncthreads();
    }
#pragma unroll
    for (int i = 0; i < 4; i++) {
        int m = m0 + ty * 4 + i;
        float2 f0 = unpack2(acc2[i][0]);
        float2 f1 = unpack2(acc2[i][1]);
        float vj[4] = {f0.x, f0.y, f1.x, f1.y};
#pragma unroll
        for (int j = 0; j < 4; j++) {
            int n = n0 + tx * 4 + j;
            float v = vj[j];
            if (bias1) v += bias1[n];
            if (bias2) v += bias2[n];
            C[(size_t)m * N + n] = v;
        }
    }
}

// ---------------- SGEMM: C[M][N] = A @ B, B is [K][N], f32x2 ----------------
__global__ void gemm_nn(const float* __restrict__ A, const float* __restrict__ B,
                        float* __restrict__ C, int M, int N, int K)
{
    __shared__ float As[16][68];
    __shared__ float Bs[16][68];
    const int m0 = blockIdx.y * 64, n0 = blockIdx.x * 64;
    const int t = threadIdx.x;
    const int tx = t & 15, ty = t >> 4;
    unsigned long long acc2[4][2];
#pragma unroll
    for (int i = 0; i < 4; i++) { acc2[i][0] = 0ull; acc2[i][1] = 0ull; }
    const int lm = t >> 2, lk = (t & 3) * 4;
    const int bk = t >> 4, bn = (t & 15) * 4;
    for (int k0 = 0; k0 < K; k0 += 16) {
        float4 av = *(const float4*)(A + (size_t)(m0 + lm) * K + k0 + lk);
        As[lk + 0][lm] = av.x; As[lk + 1][lm] = av.y; As[lk + 2][lm] = av.z; As[lk + 3][lm] = av.w;
        float4 bv = *(const float4*)(B + (size_t)(k0 + bk) * N + n0 + bn);
        *(float4*)&Bs[bk][bn] = bv;
        __syncthreads();
#pragma unroll
        for (int kk = 0; kk < 16; kk++) {
            float4 a4 = *(const float4*)&As[kk][ty * 4];
            ulonglong2 b2 = *(const ulonglong2*)&Bs[kk][tx * 4];
            float aa[4] = {a4.x, a4.y, a4.z, a4.w};
#pragma unroll
            for (int i = 0; i < 4; i++) {
                unsigned long long ap = pack2(aa[i]);
                ffma2(acc2[i][0], ap, b2.x);
                ffma2(acc2[i][1], ap, b2.y);
            }
        }
        __syncthreads();
    }
#pragma unroll
    for (int i = 0; i < 4; i++) {
        int m = m0 + ty * 4 + i;
        float2 f0 = unpack2(acc2[i][0]);
        float2 f1 = unpack2(acc2[i][1]);
        C[(size_t)m * N + (n0 + tx * 4 + 0)] = f0.x;
        C[(size_t)m * N + (n0 + tx * 4 + 1)] = f0.y;
        C[(size_t)m * N + (n0 + tx * 4 + 2)] = f1.x;
        C[(size_t)m * N + (n0 + tx * 4 + 3)] = f1.y;
    }
}

// ---------------- persistent encoder v7: 4 batches/thread, weight-LDS amortized 4x ----------------
// Thread (kq = t>>4 in 0..31 -> 16 k; bq = t&15 -> batches bq*4..+3). 64 accumulators (32 FFMA2).
// Per k: 1 coalesced LDG.128 of h + 4 LDS.128 weights feed 64 MAC (vs 16 before).
// Weight-LDS warp-inst per SM per step: 4096 -> 1024.
// dyn smem: wsm[512*16=8192] | psum[32*64*18=36864]  (180.2 KB)
__global__ __launch_bounds__(512, 1) void enc_persist(
    const float* __restrict__ xproj, const float* __restrict__ Whh,
    const int* __restrict__ src,
    float* __restrict__ hT0, float* __restrict__ hT1,
    float* __restrict__ cT, float* __restrict__ hs)
{
    extern __shared__ float esm[];
    float* wsm = esm;            // [k][16]
    float* psum = esm + 8192;    // [(kq*64 + b)*18 + c], kq 0..31
    const int t = threadIdx.x, bn = blockIdx.x;
    unsigned mygen = ld_acq(&g_gen);

    for (int i = t; i < 512 * 16; i += 512) {
        int c = i & 15, k = i >> 4;
        int q = c >> 2, jj = c & 3;
        wsm[k * 16 + c] = Whh[(size_t)(q * 512 + bn * 4 + jj) * 512 + k];
    }
    __syncthreads();

    const int kq = t >> 4;        // 0..31
    const int bq = t & 15;        // batches bq*4..+3
    const int k0 = kq * 16;
    const int eb = t >> 2, ejj = t & 3, ej = bn * 4 + ejj;   // epilogue roles (t<256)

    for (int tt = 0; tt < LSRC; tt++) {
        const float* hin = (tt & 1) ? hT1 : hT0;
        float* hout = (tt & 1) ? hT0 : hT1;
        const float* xp = xproj + (size_t)tt * 64 * 2048;
        float xpr0 = 0.f, xpr1 = 0.f, xpr2 = 0.f, xpr3 = 0.f;
        if (t < 256) {
            xpr0 = xp[eb * 2048 + 0 * 512 + bn * 4 + ejj];
            xpr1 = xp[eb * 2048 + 1 * 512 + bn * 4 + ejj];
            xpr2 = xp[eb * 2048 + 2 * 512 + bn * 4 + ejj];
            xpr3 = xp[eb * 2048 + 3 * 512 + bn * 4 + ejj];
        }

        unsigned long long acc[4][8];
#pragma unroll
        for (int b = 0; b < 4; b++)
#pragma unroll
            for (int p = 0; p < 8; p++) acc[b][p] = 0ull;

        const float* hp = hin + (size_t)k0 * 64 + bq * 4;
#pragma unroll 4
        for (int k = 0; k < 16; k++) {
            float4 hv = *(const float4*)(hp + (size_t)k * 64);
            const ulonglong2* w2 = (const ulonglong2*)(wsm + (size_t)(k0 + k) * 16);
            ulonglong2 wa = w2[0], wb = w2[1], wc = w2[2], wd = w2[3];
            float hh[4] = {hv.x, hv.y, hv.z, hv.w};
#pragma unroll
            for (int b = 0; b < 4; b++) {
                unsigned long long h2 = pack2(hh[b]);
                ffma2(acc[b][0], h2, wa.x); ffma2(acc[b][1], h2, wa.y);
                ffma2(acc[b][2], h2, wb.x); ffma2(acc[b][3], h2, wb.y);
                ffma2(acc[b][4], h2, wc.x); ffma2(acc[b][5], h2, wc.y);
                ffma2(acc[b][6], h2, wd.x); ffma2(acc[b][7], h2, wd.y);
            }
        }
#pragma unroll
        for (int b = 0; b < 4; b++) {
            float* psr = psum + (size_t)(kq * 64 + bq * 4 + b) * 18;
#pragma unroll
            for (int p = 0; p < 8; p++) {
                float2 f = unpack2(acc[b][p]);
                *(float2*)&psr[2 * p] = f;
            }
        }
        __syncthreads();
        if (t < 256) {
            float gi = xpr0, gf = xpr1, gg = xpr2, go = xpr3;
#pragma unroll
            for (int r = 0; r < 32; r++) {
                const float* pr = psum + (size_t)(r * 64 + eb) * 18;
                gi += pr[ejj];
                gf += pr[4 + ejj];
                gg += pr[8 + ejj];
                go += pr[12 + ejj];
            }
            float cold = cT[ej * 64 + eb];
            float cn = sigf(gf) * cold + sigf(gi) * tanhf(gg);
            float hn = sigf(go) * tanhf(cn);
            float m = (src[tt * 64 + eb] > 0) ? 1.0f : 0.0f;
            hout[ej * 64 + eb] = m * hn + (1.0f - m) * hin[ej * 64 + eb];
            cT[ej * 64 + eb] = m * cn + (1.0f - m) * cold;
            hs[((size_t)tt * 64 + eb) * 512 + ej] = hn * m;
        }
        gridbar(gridDim.x, mygen);
    }
}

// ---------------- persistent decoder: 512 threads, all 32 steps, f32x2 (R11) ----------------
#define DEC_POOL_OFF 16400
#define DEC_POOL_FLOATS 36992
#define DEC_SMEM_FLOATS (DEC_POOL_OFF + DEC_POOL_FLOATS)

__global__ __launch_bounds__(512, 1) void dec_persist(
    const float* __restrict__ dec_emb,
    const float* __restrict__ Wih, const float* __restrict__ Whh,
    const float* __restrict__ bih, const float* __restrict__ bhh,
    const float* __restrict__ Wc, const float* __restrict__ bc,
    const float* __restrict__ outW, const float* __restrict__ outb,
    const float* __restrict__ hsW, const float* __restrict__ hs,
    const int* __restrict__ src,
    const float* __restrict__ encH,
    float* __restrict__ dT0, float* __restrict__ dT1, float* __restrict__ cT,
    float* __restrict__ hdrow, float* __restrict__ xT,
    float* __restrict__ ctxT, float* __restrict__ attT,
    float* __restrict__ partV, int* __restrict__ partI,
    float* __restrict__ out)
{
    extern __shared__ float dyn[];
    float* wih_s = dyn;          // [k][16]
    float* whh_s = dyn + 8192;   // [k][16]
    float* bsum = dyn + 16384;   // [16]
    float* pool = dyn + DEC_POOL_OFF;

    const int t = threadIdx.x, bid = blockIdx.x;
    const unsigned gd = gridDim.x;
    unsigned mygen = ld_acq(&g_gen);

    if (bid < 128) {
        for (int i = t; i < 512 * 16; i += 512) {
            int c = i & 15, k = i >> 4;
            int q = c >> 2, jj = c & 3;
            int gc = q * 512 + bid * 4 + jj;
            wih_s[k * 16 + c] = Wih[(size_t)gc * 512 + k];
            whh_s[k * 16 + c] = Whh[(size_t)gc * 512 + k];
        }
        if (t < 16) {
            int q = t >> 2, jj = t & 3;
            int gc = q * 512 + bid * 4 + jj;
            bsum[t] = bih[gc] + bhh[gc];
        }
    }
    if (bid < 64) {
        xT[t * 64 + bid] = dec_emb[512 + t];   // row BOS=1
    }
    gridbar(gd, mygen);

    const int b = t & 63, kq = t >> 6, k0 = kq * 64;
    const int eb = t >> 2, ejj = t & 3;

    for (int s = 0; s < TDEC; s++) {
        const float* hdin = (s == 0) ? encH : ((s & 1) ? dT1 : dT0);
        float* hdout = (s & 1) ? dT0 : dT1;

        // ---- phase A: decoder LSTM cell (f32x2) ----
        if (bid < 128) {
            unsigned long long accp[8];
#pragma unroll
            for (int p = 0; p < 8; p++) accp[p] = 0ull;
            const float* xp = xT + (size_t)k0 * 64 + b;
#pragma unroll
            for (int k = 0; k < 64; k += 8) {
                float xreg[8];
#pragma unroll
                for (int u = 0; u < 8; u++) xreg[u] = xp[(k + u) * 64];
#pragma unroll
                for (int u = 0; u < 8; u++) {
                    const ulonglong2* w2 = (const ulonglong2*)(wih_s + (size_t)(k0 + k + u) * 16);
                    ulonglong2 wa = w2[0], wb = w2[1], wc = w2[2], wd = w2[3];
                    unsigned long long h2 = pack2(xreg[u]);
                    ffma2(accp[0], h2, wa.x); ffma2(accp[1], h2, wa.y);
                    ffma2(accp[2], h2, wb.x); ffma2(accp[3], h2, wb.y);
                    ffma2(accp[4], h2, wc.x); ffma2(accp[5], h2, wc.y);
                    ffma2(accp[6], h2, wd.x); ffma2(accp[7], h2, wd.y);
                }
            }
            const float* hp = hdin + (size_t)k0 * 64 + b;
#pragma unroll
            for (int k = 0; k < 64; k += 8) {
                float hreg[8];
#pragma unroll
                for (int u = 0; u < 8; u++) hreg[u] = hp[(k + u) * 64];
#pragma unroll
                for (int u = 0; u < 8; u++) {
                    const ulonglong2* w2 = (const ulonglong2*)(whh_s + (size_t)(k0 + k + u) * 16);
                    ulonglong2 wa = w2[0], wb = w2[1], wc = w2[2], wd = w2[3];
                    unsigned long long h2 = pack2(hreg[u]);
                    ffma2(accp[0], h2, wa.x); ffma2(accp[1], h2, wa.y);
                    ffma2(accp[2], h2, wb.x); ffma2(accp[3], h2, wb.y);
                    ffma2(accp[4], h2, wc.x); ffma2(accp[5], h2, wc.y);
                    ffma2(accp[6], h2, wd.x); ffma2(accp[7], h2, wd.y);
                }
            }
            {
                float* ps = pool + (size_t)(kq * 64 + b) * 17;
#pragma unroll
                for (int p = 0; p < 8; p++) {
                    float2 f = unpack2(accp[p]);
                    ps[2 * p] = f.x;
                    ps[2 * p + 1] = f.y;
                }
            }
            __syncthreads();
            if (t < 256) {
                const int j = bid * 4 + ejj;
                float gi = bsum[ejj], gf = bsum[4 + ejj], gg = bsum[8 + ejj], go = bsum[12 + ejj];
#pragma unroll
                for (int r = 0; r < 8; r++) {
                    const float* pr = pool + (size_t)(r * 64 + eb) * 17;
                    gi += pr[ejj];
                    gf += pr[4 + ejj];
                    gg += pr[8 + ejj];
                    go += pr[12 + ejj];
                }
                float cold = cT[j * 64 + eb];
                float cn = sigf(gf) * cold + sigf(gi) * tanhf(gg);
                float hn = sigf(go) * tanhf(cn);
                hdout[j * 64 + eb] = hn;
                hdrow[eb * 512 + j] = hn;
                cT[j * 64 + eb] = cn;
            }
        }
        gridbar(gd, mygen);

        // ---- phase B: attention scores + softmax + context ----
        if (bid < 64) {
            float* hd_sm = pool;
            float* sc = pool + 512;
            float* red = pool + 768;
            hd_sm[t] = hdrow[bid * 512 + t];
            __syncthreads();
            const int w = t >> 5, lane = t & 31;
            for (int l = w; l < 256; l += 16) {
                const float* hw = hsW + ((size_t)l * 64 + bid) * 512;
                float sv = 0.0f;
#pragma unroll
                for (int kk = 0; kk < 16; kk++) sv += hd_sm[lane + kk * 32] * hw[lane + kk * 32];
#pragma unroll
                for (int o = 16; o; o >>= 1) sv += __shfl_xor_sync(0xffffffffu, sv, o);
                if (lane == 0) sc[l] = sv;
            }
            __syncthreads();
            float my = 0.0f;
            if (t < 256) {
                my = sc[t];
                float v = my;
#pragma unroll
                for (int o = 16; o; o >>= 1) v = fmaxf(v, __shfl_xor_sync(0xffffffffu, v, o));
                if (lane == 0) red[w] = v;
            }
            __syncthreads();
            float mx = red[0];
#pragma unroll
            for (int i = 1; i < 8; i++) mx = fmaxf(mx, red[i]);
            if (t < 256) {
                float ev = expf(my - mx) * (src[t * 64 + bid] > 0 ? 1.0f : 0.0f);
                sc[t] = ev;
                float sv = ev;
#pragma unroll
                for (int o = 16; o; o >>= 1) sv += __shfl_xor_sync(0xffffffffu, sv, o);
                if (lane == 0) red[8 + w] = sv;
            }
            __syncthreads();
            float tot = 0.0f;
#pragma unroll
            for (int i = 0; i < 8; i++) tot += red[8 + i];
            float inv = 1.0f / tot;
            {
                float a = 0.0f;
                const float* hp2 = hs + (size_t)bid * 512 + t;
                for (int l = 0; l < 256; l++) a += sc[l] * hp2[(size_t)l * 64 * 512];
                ctxT[t * 64 + bid] = a * inv;
            }
        }
        gridbar(gd, mygen);

        // ---- phase C: attT = tanh(cat @ Wc + bc) ----
        if (bid < 128) {
            float* As = pool;
            float* Ws = pool + 64 * 68;
            const int col = t & 3, brow = t >> 2;
            float acc = 0.0f;
            for (int kc = 0; kc < 16; kc++) {
                __syncthreads();
                if (t < 256) {
#pragma unroll
                    for (int r = 0; r < 4; r++) {
                        int idx4 = t + r * 256;
                        int row = idx4 >> 4, b4 = (idx4 & 15) * 4;
                        int k = kc * 64 + row;
                        const float* sp = (k < 512) ? (ctxT + (size_t)k * 64)
                                                    : (hdout + (size_t)(k - 512) * 64);
                        *(float4*)&As[row * 68 + b4] = *(const float4*)(sp + b4);
                    }
                    {
                        int kk = t >> 2, c = t & 3;
                        Ws[kk * 4 + c] = Wc[(size_t)(kc * 64 + kk) * 512 + bid * 4 + c];
                    }
                }
                __syncthreads();
                if (t < 256) {
#pragma unroll 8
                    for (int kk = 0; kk < 64; kk++)
                        acc += As[kk * 68 + brow] * Ws[kk * 4 + col];
                }
            }
            if (t < 256)
                attT[(bid * 4 + col) * 64 + brow] = tanhf(acc + bc[bid * 4 + col]);
        }
        gridbar(gd, mygen);

        // ---- phase D: logits GEMM (f32x2) + fused argmax partials ----
        {
            float* attS = pool;                 // [512][64]
            float* BsBuf = pool + 32768;        // 2 x [16][128]
            float* rv = pool + 36864;           // [64]
            int* ri = (int*)(pool + 36928);     // [64]
            const int tx = t & 31, ty = t >> 5;
            const int dn = t >> 2, dkg = (t & 3) * 4;

            for (int i = t * 4; i < 32768; i += 2048) {
                int k = i >> 6, bb = i & 63;
                *(float4*)&attS[k * 64 + bb] = *(const float4*)(attT + (size_t)k * 64 + bb);
            }
            __syncthreads();

            float bestv[4];
            int besti[4];
#pragma unroll
            for (int i = 0; i < 4; i++) { bestv[i] = -FLT_MAX; besti[i] = 0x7fffffff; }

            for (int tile = bid; tile < VOCAB / 128; tile += gd) {
                const int n0 = tile * 128;
                const float* wrow = outW + (size_t)(n0 + dn) * 512 + dkg;
                unsigned long long acc2[4][2];
#pragma unroll
                for (int i = 0; i < 4; i++) { acc2[i][0] = 0ull; acc2[i][1] = 0ull; }
                {
                    float4 wv = *(const float4*)(wrow);
                    float* Bs0 = BsBuf;
                    Bs0[(dkg + 0) * 128 + dn] = wv.x; Bs0[(dkg + 1) * 128 + dn] = wv.y;
                    Bs0[(dkg + 2) * 128 + dn] = wv.z; Bs0[(dkg + 3) * 128 + dn] = wv.w;
                }
                __syncthreads();
                for (int c = 0; c < 32; c++) {
                    float4 wv;
                    if (c < 31) wv = *(const float4*)(wrow + (c + 1) * 16);
                    const float* Bs = BsBuf + (c & 1) * 2048;
                    const float* Ac = attS + (size_t)c * 16 * 64;
#pragma unroll
                    for (int kk = 0; kk < 16; kk++) {
                        float4 a4 = *(const float4*)&Ac[kk * 64 + ty * 4];
                        ulonglong2 b2 = *(const ulonglong2*)&Bs[kk * 128 + tx * 4];
                        float aa[4] = {a4.x, a4.y, a4.z, a4.w};
#pragma unroll
                        for (int i = 0; i < 4; i++) {
                            unsigned long long ap = pack2(aa[i]);
                            ffma2(acc2[i][0], ap, b2.x);
                            ffma2(acc2[i][1], ap, b2.y);
                        }
                    }
                    if (c < 31) {
                        float* Bn = BsBuf + ((c + 1) & 1) * 2048;
                        Bn[(dkg + 0) * 128 + dn] = wv.x; Bn[(dkg + 1) * 128 + dn] = wv.y;
                        Bn[(dkg + 2) * 128 + dn] = wv.z; Bn[(dkg + 3) * 128 + dn] = wv.w;
                    }
                    __syncthreads();
                }
#pragma unroll
                for (int i = 0; i < 4; i++) {
                    int bb2 = ty * 4 + i;
                    float2 f0 = unpack2(acc2[i][0]);
                    float2 f1 = unpack2(acc2[i][1]);
                    float vj[4] = {f0.x, f0.y, f1.x, f1.y};
#pragma unroll
                    for (int j = 0; j < 4; j++) {
                        int n = n0 + tx * 4 + j;
                        float v = vj[j] + outb[n];
                        out[((size_t)s * 64 + bb2) * VOCAB + n] = v;
                        if (v > bestv[i]) { bestv[i] = v; besti[i] = n; }
                    }
                }
            }
#pragma unroll
            for (int i = 0; i < 4; i++) {
                float v = bestv[i]; int ix = besti[i];
#pragma unroll
                for (int o = 16; o; o >>= 1) {
                    float ov = __shfl_xor_sync(0xffffffffu, v, o);
                    int oi = __shfl_xor_sync(0xffffffffu, ix, o);
                    if (ov > v || (ov == v && oi < ix)) { v = ov; ix = oi; }
                }
                bestv[i] = v; besti[i] = ix;
            }
            __syncthreads();
            if ((t & 31) == 0) {
#pragma unroll
                for (int i = 0; i < 4; i++) { rv[ty * 4 + i] = bestv[i]; ri[ty * 4 + i] = besti[i]; }
            }
            __syncthreads();
            if (t < 64) {
                partV[bid * 64 + t] = rv[t];
                partI[bid * 64 + t] = ri[t];
            }
        }
        gridbar(gd, mygen);

        // ---- phase E: global argmax + next embedding ----
        if (bid < 64) {
            float* ev = pool;
            int* ei = (int*)(pool + 512);
            float bv = -FLT_MAX; int bi = 0x7fffffff;
            for (unsigned g = t; g < gd; g += 512) {
                float v = partV[g * 64 + bid]; int ix = partI[g * 64 + bid];
                if (v > bv || (v == bv && ix < bi)) { bv = v; bi = ix; }
            }
            ev[t] = bv; ei[t] = bi;
            __syncthreads();
            for (int s2 = 256; s2; s2 >>= 1) {
                if (t < s2) {
                    float v = ev[t + s2]; int ix = ei[t + s2];
                    if (v > ev[t] || (v == ev[t] && ix < ei[t])) { ev[t] = v; ei[t] = ix; }
                }
                __syncthreads();
            }
            int ynext = ei[0];
            xT[t * 64 + bid] = dec_emb[(size_t)ynext * 512 + t];
        }
        gridbar(gd, mygen);
    }
}

// ---------------- host launch ----------------
extern "C" void kernel_launch(void* const* d_in, const int* in_sizes, int n_in,
                              void* d_out, int out_size)
{
    const int*   src     = (const int*)d_in[0];
    const float* enc_emb = (const float*)d_in[1];
    const float* enc_Wih = (const float*)d_in[2];
    const float* enc_Whh = (const float*)d_in[3];
    const float* enc_bih = (const float*)d_in[4];
    const float* enc_bhh = (const float*)d_in[5];
    const float* dec_emb = (const float*)d_in[6];
    const float* dec_Wih = (const float*)d_in[7];
    const float* dec_Whh = (const float*)d_in[8];
    const float* dec_bih = (const float*)d_in[9];
    const float* dec_bhh = (const float*)d_in[10];
    const float* W_a     = (const float*)d_in[11];
    const float* W_c     = (const float*)d_in[12];
    const float* b_c     = (const float*)d_in[13];
    const float* out_W   = (const float*)d_in[14];
    const float* out_b   = (const float*)d_in[15];
    float* out = (float*)d_out;

    float *xproj, *hs, *hsW, *hT0, *hT1, *cT, *dT0, *dT1, *hdrow, *xT, *ctxT, *attT, *partV;
    int* partI;
    cudaGetSymbolAddress((void**)&xproj, g_xproj);
    cudaGetSymbolAddress((void**)&hs, g_hs);
    cudaGetSymbolAddress((void**)&hsW, g_hsW);
    cudaGetSymbolAddress((void**)&hT0, g_hT0);
    cudaGetSymbolAddress((void**)&hT1, g_hT1);
    cudaGetSymbolAddress((void**)&cT, g_cT);
    cudaGetSymbolAddress((void**)&dT0, g_dT0);
    cudaGetSymbolAddress((void**)&dT1, g_dT1);
    cudaGetSymbolAddress((void**)&hdrow, g_hdrow);
    cudaGetSymbolAddress((void**)&xT, g_xT);
    cudaGetSymbolAddress((void**)&ctxT, g_ctxT);
    cudaGetSymbolAddress((void**)&attT, g_attT);
    cudaGetSymbolAddress((void**)&partV, g_partV);
    cudaGetSymbolAddress((void**)&partI, g_partI);

    int nsm = 148;
    cudaDeviceGetAttribute(&nsm, cudaDevAttrMultiProcessorCount, 0);
    int gdec = nsm;
    if (gdec > MAXGRID) gdec = MAXGRID;
    if (gdec < 128) gdec = 128;

    const int enc_smem = (8192 + 32 * 64 * 18) * 4;   // 180.2 KB
    cudaFuncSetAttribute(enc_persist, cudaFuncAttributeMaxDynamicSharedMemorySize, enc_smem);
    cudaFuncSetAttribute(dec_persist, cudaFuncAttributeMaxDynamicSharedMemorySize,
                         DEC_SMEM_FLOATS * 4);

    // 6-launch sequence: ncu (-s 5 -c 1 => my 4th launch) lands on enc_persist
    gemm_nt<true><<<dim3(GATES / 64, 128), 256>>>(
        enc_emb, src, enc_Wih, enc_bih, enc_bhh, xproj, LSRC * BATCH, GATES, HID);
    gemm_nt<true><<<dim3(GATES / 64, 128), 256>>>(
        enc_emb, src + 8192, enc_Wih, enc_bih, enc_bhh,
        xproj + (size_t)8192 * GATES, LSRC * BATCH, GATES, HID);

    init_kernel<<<128, 256>>>(hT0, cT);

    enc_persist<<<128, 512, enc_smem>>>(xproj, enc_Whh, src, hT0, hT1, cT, hs);

    gemm_nn<<<dim3(HID / 64, (LSRC * BATCH) / 64), 256>>>(hs, W_a, hsW, LSRC * BATCH, HID, HID);

    dec_persist<<<gdec, 512, DEC_SMEM_FLOATS * 4>>>(
        dec_emb, dec_Wih, dec_Whh, dec_bih, dec_bhh,
        W_c, b_c, out_W, out_b, hsW, hs, src,
        hT0, dT0, dT1, cT, hdrow, xT, ctxT, attT, partV, partI, out);
}